// round 16
// baseline (speedup 1.0000x reference)
#include <cuda_runtime.h>
#include <cuda_bf16.h>
#include <math.h>
#include <stdint.h>

#define N_NODES 50000
#define HIDDEN  128
#define FFN     256
#define LN_EPS  1e-5f
#define MAX_E   524288
#define NB_SCAN 196   // ceil(50000/256)

// ---------------- scratch (static device globals; no allocation) ----------
__device__ __align__(16) float g_h [(size_t)N_NODES * FFN];          // gelu out (fp32)
__device__ __align__(16) __nv_bfloat16 g_xw[(size_t)N_NODES * FFN];  // gating gemm out
__device__ float  g_dinv[N_NODES];
__device__ int    g_cnt [N_NODES];
__device__ int    g_cur [N_NODES];
__device__ int    g_rowptr[N_NODES + 1];
__device__ int    g_bsum[256];
__device__ int    g_csr [MAX_E];
__device__ float2 g_st1[N_NODES];   // LN1 (mu, rstd) of x rows
__device__ float2 g_st2[N_NODES];   // (sum, sumsq) of h rows, filled by GEMM1
__device__ int    g_is64;

// ---------------- init: LN1 stats + zero hist/sums + dtype detect -----------
__global__ void k_init(const float* __restrict__ x, const unsigned int* __restrict__ w,
                       int nslots) {
    int gtid = blockIdx.x * blockDim.x + threadIdx.x;
    int warp = gtid >> 5;
    int lane = threadIdx.x & 31;

    if (gtid < N_NODES) {
        g_cnt[gtid] = 0;
        g_st2[gtid] = make_float2(0.f, 0.f);
    }
    if (warp < N_NODES) {
        float4 v = ((const float4*)(x + (size_t)warp * HIDDEN))[lane];
        float s  = v.x + v.y + v.z + v.w;
        float sq = v.x * v.x + v.y * v.y + v.z * v.z + v.w * v.w;
        #pragma unroll
        for (int o = 16; o; o >>= 1) {
            s  += __shfl_xor_sync(0xffffffffu, s,  o);
            sq += __shfl_xor_sync(0xffffffffu, sq, o);
        }
        if (lane == 0) {
            float mu  = s * (1.0f / HIDDEN);
            float var = sq * (1.0f / HIDDEN) - mu * mu;
            g_st1[warp] = make_float2(mu, rsqrtf(var + LN_EPS));
        }
    }
    if (blockIdx.x == 0) {
        __shared__ unsigned int red[256];
        unsigned int acc = 0;
        for (int j = threadIdx.x; j < nslots; j += blockDim.x) acc |= w[2 * j + 1];
        red[threadIdx.x] = acc;
        __syncthreads();
        for (int s = 128; s > 0; s >>= 1) {
            if (threadIdx.x < s) red[threadIdx.x] |= red[threadIdx.x + s];
            __syncthreads();
        }
        if (threadIdx.x == 0) g_is64 = (red[0] == 0u) ? 1 : 0;
    }
}

// ---------------- serial CSR tail -------------------------------------------
__global__ void k_scan3(int E) {
    __shared__ int sh[256];
    int t = threadIdx.x;
    int v = (t < NB_SCAN) ? g_bsum[t] : 0;
    sh[t] = v;
    __syncthreads();
    #pragma unroll
    for (int off = 1; off < 256; off <<= 1) {
        int addend = (t >= off) ? sh[t - off] : 0;
        __syncthreads();
        sh[t] += addend;
        __syncthreads();
    }
    int boff = (blockIdx.x > 0) ? sh[blockIdx.x - 1] : 0;
    int i = blockIdx.x * 256 + t;
    if (i < N_NODES) {
        g_rowptr[i] += boff;
        g_dinv[i] = rsqrtf((float)g_cnt[i] + 2.0f);
        g_cur[i] = 0;
    }
    if (i == 0) g_rowptr[N_NODES] = E;
}
__global__ void k_fill(const void* __restrict__ eidx, int E) {
    int e = blockIdx.x * blockDim.x + threadIdx.x;
    if (e >= E) return;
    int s, d;
    if (g_is64) {
        const long long* p = (const long long*)eidx;
        s = (int)p[e]; d = (int)p[E + e];
    } else {
        const int* p = (const int*)eidx;
        s = p[e]; d = p[E + e];
    }
    int pos = g_rowptr[d] + atomicAdd(&g_cur[d], 1);
    g_csr[pos] = s;
}

// ---------------- mma / ldmatrix helpers ------------------------------------
__device__ __forceinline__ float f2tf32(float x) {
    unsigned r;
    asm("cvt.rna.tf32.f32 %0, %1;" : "=r"(r) : "f"(x));
    return __uint_as_float(r);
}
__device__ __forceinline__ void mma_tf32(float* c, const unsigned* a, const unsigned* b) {
    asm volatile(
        "mma.sync.aligned.m16n8k8.row.col.f32.tf32.tf32.f32 "
        "{%0,%1,%2,%3}, {%4,%5,%6,%7}, {%8,%9}, {%0,%1,%2,%3};"
        : "+f"(c[0]), "+f"(c[1]), "+f"(c[2]), "+f"(c[3])
        : "r"(a[0]), "r"(a[1]), "r"(a[2]), "r"(a[3]), "r"(b[0]), "r"(b[1]));
}
__device__ __forceinline__ void mma_bf16(float* c, const unsigned* a, const unsigned* b) {
    asm volatile(
        "mma.sync.aligned.m16n8k16.row.col.f32.bf16.bf16.f32 "
        "{%0,%1,%2,%3}, {%4,%5,%6,%7}, {%8,%9}, {%0,%1,%2,%3};"
        : "+f"(c[0]), "+f"(c[1]), "+f"(c[2]), "+f"(c[3])
        : "r"(a[0]), "r"(a[1]), "r"(a[2]), "r"(a[3]), "r"(b[0]), "r"(b[1]));
}
__device__ __forceinline__ unsigned pack_bf16(float a, float b) {
    unsigned r;
    asm("cvt.rn.bf16x2.f32 %0, %1, %2;" : "=r"(r) : "f"(b), "f"(a));
    return r;
}
__device__ __forceinline__ void ldsm4(unsigned& r0, unsigned& r1, unsigned& r2,
                                      unsigned& r3, unsigned addr) {
    asm volatile("ldmatrix.sync.aligned.m8n8.x4.shared.b16 {%0,%1,%2,%3}, [%4];"
                 : "=r"(r0), "=r"(r1), "=r"(r2), "=r"(r3) : "r"(addr));
}
__device__ __forceinline__ float gelu_f(float v) {
    return 0.5f * v * (1.0f + erff(v * 0.70710678118654752f));
}

// ============================================================================
// GEMM1 (tf32): h_f32[M,256] = gelu(LN1(x)[M,128] @ w_in^T + b_in)
// Accumulates per-row (sum, sumsq) of gelu output into g_st2 (LN2 stats).
// Grid (391, 3): y in {0,1} = GEMM tiles; y == 2 = edge-histogram blocks.
// ============================================================================
__global__ __launch_bounds__(256) void k_gemm1(
    const float* __restrict__ A, const float* __restrict__ W,
    const float* __restrict__ bias, float* __restrict__ C, int M,
    const float2* __restrict__ stats, const float* __restrict__ lng,
    const float* __restrict__ lnb, const void* __restrict__ eidx, int E) {
    const int K = 128, BK = 32, PITCH = 36;
    __shared__ float As[128 * PITCH];
    __shared__ float Bs[128 * PITCH];

    // ---- piggyback: histogram of destination nodes ----
    if (blockIdx.y == 2) {
        int stride = gridDim.x * blockDim.x;
        if (g_is64) {
            const long long* p = (const long long*)eidx;
            for (int e = blockIdx.x * blockDim.x + threadIdx.x; e < E; e += stride)
                atomicAdd(&g_cnt[(int)p[E + e]], 1);
        } else {
            const int* p = (const int*)eidx;
            for (int e = blockIdx.x * blockDim.x + threadIdx.x; e < E; e += stride)
                atomicAdd(&g_cnt[p[E + e]], 1);
        }
        return;
    }

    int tid = threadIdx.x;
    int wid = tid >> 5, lane = tid & 31;
    int wm = wid >> 1, wn = wid & 1;
    int g = lane >> 2, tq = lane & 3;
    int lrow8 = lane & 7, grp = lane >> 3;
    int bm0 = blockIdx.x * 128, bn0 = blockIdx.y * 128;

    float acc[2][8][4];
    #pragma unroll
    for (int mt = 0; mt < 2; mt++)
        #pragma unroll
        for (int nt = 0; nt < 8; nt++)
            #pragma unroll
            for (int i = 0; i < 4; i++) acc[mt][nt][i] = 0.0f;

    unsigned aAddr[2], bAddr[4];
    {
        unsigned ab = (unsigned)__cvta_generic_to_shared(As);
        unsigned bb = (unsigned)__cvta_generic_to_shared(Bs);
        #pragma unroll
        for (int mt = 0; mt < 2; mt++) {
            int rowA = wm * 32 + mt * 16 + lrow8 + ((grp & 1) << 3);
            aAddr[mt] = ab + (rowA * PITCH + ((grp >> 1) << 2)) * 4;
        }
        #pragma unroll
        for (int nt2 = 0; nt2 < 4; nt2++) {
            int rowB = wn * 64 + nt2 * 16 + lrow8 + ((grp >> 1) << 3);
            bAddr[nt2] = bb + (rowB * PITCH + ((grp & 1) << 2)) * 4;
        }
    }

    int lrow = tid >> 3, lc4 = tid & 7;
    float4 ar[4], br[4];

    #pragma unroll
    for (int i = 0; i < 4; i++) {
        int row = lrow + i * 32;
        int gr = bm0 + row;
        float4 v = make_float4(0.f, 0.f, 0.f, 0.f);
        if (gr < M) {
            v = *(const float4*)(A + (size_t)gr * K + lc4 * 4);
            float2 st = stats[gr];
            float4 gg = ((const float4*)lng)[lc4];
            float4 bb = ((const float4*)lnb)[lc4];
            v.x = (v.x - st.x) * st.y * gg.x + bb.x;
            v.y = (v.y - st.x) * st.y * gg.y + bb.y;
            v.z = (v.z - st.x) * st.y * gg.z + bb.z;
            v.w = (v.w - st.x) * st.y * gg.w + bb.w;
        }
        ar[i] = v;
        br[i] = *(const float4*)(W + (size_t)(bn0 + row) * K + lc4 * 4);
    }

    #pragma unroll 1
    for (int k0 = 0; k0 < K; k0 += BK) {
        #pragma unroll
        for (int i = 0; i < 4; i++) {
            int row = lrow + i * 32;
            float* da = &As[row * PITCH + lc4 * 4];
            da[0] = f2tf32(ar[i].x); da[1] = f2tf32(ar[i].y);
            da[2] = f2tf32(ar[i].z); da[3] = f2tf32(ar[i].w);
            float* db = &Bs[row * PITCH + lc4 * 4];
            db[0] = f2tf32(br[i].x); db[1] = f2tf32(br[i].y);
            db[2] = f2tf32(br[i].z); db[3] = f2tf32(br[i].w);
        }
        __syncthreads();

        if (k0 + BK < K) {
            int kn = k0 + BK;
            #pragma unroll
            for (int i = 0; i < 4; i++) {
                int row = lrow + i * 32;
                int gr = bm0 + row;
                float4 v = make_float4(0.f, 0.f, 0.f, 0.f);
                if (gr < M) {
                    v = *(const float4*)(A + (size_t)gr * K + kn + lc4 * 4);
                    float2 st = stats[gr];
                    float4 gg = ((const float4*)lng)[kn / 4 + lc4];
                    float4 bb = ((const float4*)lnb)[kn / 4 + lc4];
                    v.x = (v.x - st.x) * st.y * gg.x + bb.x;
                    v.y = (v.y - st.x) * st.y * gg.y + bb.y;
                    v.z = (v.z - st.x) * st.y * gg.z + bb.z;
                    v.w = (v.w - st.x) * st.y * gg.w + bb.w;
                }
                ar[i] = v;
                br[i] = *(const float4*)(W + (size_t)(bn0 + row) * K + kn + lc4 * 4);
            }
        }

        #pragma unroll
        for (int ks = 0; ks < 4; ks++) {
            unsigned af[2][4], bfv[8][2];
            #pragma unroll
            for (int mt = 0; mt < 2; mt++)
                ldsm4(af[mt][0], af[mt][1], af[mt][2], af[mt][3], aAddr[mt] + ks * 32);
            #pragma unroll
            for (int nt2 = 0; nt2 < 4; nt2++) {
                unsigned r0, r1, r2, r3;
                ldsm4(r0, r1, r2, r3, bAddr[nt2] + ks * 32);
                bfv[nt2 * 2][0] = r0; bfv[nt2 * 2][1] = r1;
                bfv[nt2 * 2 + 1][0] = r2; bfv[nt2 * 2 + 1][1] = r3;
            }
            #pragma unroll
            for (int mt = 0; mt < 2; mt++)
                #pragma unroll
                for (int nt = 0; nt < 8; nt++)
                    mma_tf32(acc[mt][nt], af[mt], bfv[nt]);
        }
        __syncthreads();
    }

    // epilogue: gelu -> fp32 store + per-row (sum, sumsq) accumulation
    #pragma unroll
    for (int mt = 0; mt < 2; mt++) {
        #pragma unroll
        for (int half = 0; half < 2; half++) {
            int r = bm0 + wm * 32 + mt * 16 + half * 8 + g;
            float s = 0.f, sq = 0.f;
            float v0s[8], v1s[8];
            #pragma unroll
            for (int nt = 0; nt < 8; nt++) {
                int c0 = bn0 + wn * 64 + nt * 8 + 2 * tq;
                float v0 = gelu_f(acc[mt][nt][half * 2 + 0] + bias[c0]);
                float v1 = gelu_f(acc[mt][nt][half * 2 + 1] + bias[c0 + 1]);
                v0s[nt] = v0; v1s[nt] = v1;
                s += v0 + v1;
                sq += v0 * v0 + v1 * v1;
            }
            if (r < M) {
                #pragma unroll
                for (int nt = 0; nt < 8; nt++) {
                    int c0 = bn0 + wn * 64 + nt * 8 + 2 * tq;
                    C[(size_t)r * FFN + c0]     = v0s[nt];
                    C[(size_t)r * FFN + c0 + 1] = v1s[nt];
                }
            }
            s  += __shfl_xor_sync(0xffffffffu, s, 1);
            s  += __shfl_xor_sync(0xffffffffu, s, 2);
            sq += __shfl_xor_sync(0xffffffffu, sq, 1);
            sq += __shfl_xor_sync(0xffffffffu, sq, 2);
            if (tq == 0 && r < M) {
                atomicAdd(&g_st2[r].x, s);
                atomicAdd(&g_st2[r].y, sq);
            }
        }
    }
}

// ============================================================================
// GEMM2 (bf16 mma): xw_bf16[M,256] = LN2(h)[M,256] @ w_gcn^T
// Grid (391, 3): y in {0,1} = GEMM tiles; y == 2, x < 196 = scan1 blocks.
// ============================================================================
__global__ __launch_bounds__(256) void k_gemm2(
    const float* __restrict__ A, const float* __restrict__ W,
    __nv_bfloat16* __restrict__ C, int M,
    const float2* __restrict__ sums, const float* __restrict__ lng,
    const float* __restrict__ lnb) {
    const int K = 256, BK = 32, PW = 20;
    __shared__ unsigned As[128 * PW];
    __shared__ unsigned Bs[128 * PW];

    // ---- piggyback: scan1 (hist complete at previous kernel boundary) ----
    if (blockIdx.y == 2) {
        if (blockIdx.x >= NB_SCAN) return;
        int* sh = (int*)As;
        int t = threadIdx.x;
        int i = blockIdx.x * 256 + t;
        int v = (i < N_NODES) ? g_cnt[i] : 0;
        sh[t] = v;
        __syncthreads();
        #pragma unroll
        for (int off = 1; off < 256; off <<= 1) {
            int addend = (t >= off) ? sh[t - off] : 0;
            __syncthreads();
            sh[t] += addend;
            __syncthreads();
        }
        if (i < N_NODES) g_rowptr[i] = sh[t] - v;
        if (t == 255) g_bsum[blockIdx.x] = sh[255];
        return;
    }

    int tid = threadIdx.x;
    int wid = tid >> 5, lane = tid & 31;
    int wm = wid >> 1, wn = wid & 1;
    int g = lane >> 2, tq = lane & 3;
    int lrow8 = lane & 7, grp = lane >> 3;
    int bm0 = blockIdx.x * 128, bn0 = blockIdx.y * 128;

    float acc[2][8][4];
    #pragma unroll
    for (int mt = 0; mt < 2; mt++)
        #pragma unroll
        for (int nt = 0; nt < 8; nt++)
            #pragma unroll
            for (int i = 0; i < 4; i++) acc[mt][nt][i] = 0.0f;

    unsigned aAddr[2], bAddr[4];
    {
        unsigned ab = (unsigned)__cvta_generic_to_shared(As);
        unsigned bb = (unsigned)__cvta_generic_to_shared(Bs);
        #pragma unroll
        for (int mt = 0; mt < 2; mt++) {
            int rowA = wm * 32 + mt * 16 + lrow8 + ((grp & 1) << 3);
            aAddr[mt] = ab + rowA * (PW * 4) + ((grp >> 1) << 4);
        }
        #pragma unroll
        for (int nt2 = 0; nt2 < 4; nt2++) {
            int rowB = wn * 64 + nt2 * 16 + lrow8 + ((grp >> 1) << 3);
            bAddr[nt2] = bb + rowB * (PW * 4) + ((grp & 1) << 4);
        }
    }

    int lrow = tid >> 3, lc4 = tid & 7;
    float4 ar[4], br[4];

    #pragma unroll
    for (int i = 0; i < 4; i++) {
        int row = lrow + i * 32;
        int gr = bm0 + row;
        float4 v = make_float4(0.f, 0.f, 0.f, 0.f);
        if (gr < M) {
            v = *(const float4*)(A + (size_t)gr * K + lc4 * 4);
            float2 sm = sums[gr];
            float mu = sm.x * (1.0f / 256.0f);
            float rstd = rsqrtf(sm.y * (1.0f / 256.0f) - mu * mu + LN_EPS);
            float4 gg = ((const float4*)lng)[lc4];
            float4 bb = ((const float4*)lnb)[lc4];
            v.x = (v.x - mu) * rstd * gg.x + bb.x;
            v.y = (v.y - mu) * rstd * gg.y + bb.y;
            v.z = (v.z - mu) * rstd * gg.z + bb.z;
            v.w = (v.w - mu) * rstd * gg.w + bb.w;
        }
        ar[i] = v;
        br[i] = *(const float4*)(W + (size_t)(bn0 + row) * K + lc4 * 4);
    }

    #pragma unroll 1
    for (int k0 = 0; k0 < K; k0 += BK) {
        #pragma unroll
        for (int i = 0; i < 4; i++) {
            int row = lrow + i * 32;
            As[row * PW + lc4 * 2]     = pack_bf16(ar[i].x, ar[i].y);
            As[row * PW + lc4 * 2 + 1] = pack_bf16(ar[i].z, ar[i].w);
            Bs[row * PW + lc4 * 2]     = pack_bf16(br[i].x, br[i].y);
            Bs[row * PW + lc4 * 2 + 1] = pack_bf16(br[i].z, br[i].w);
        }
        __syncthreads();

        if (k0 + BK < K) {
            int kn = k0 + BK;
            #pragma unroll
            for (int i = 0; i < 4; i++) {
                int row = lrow + i * 32;
                int gr = bm0 + row;
                float4 v = make_float4(0.f, 0.f, 0.f, 0.f);
                if (gr < M) {
                    v = *(const float4*)(A + (size_t)gr * K + kn + lc4 * 4);
                    float2 sm = sums[gr];
                    float mu = sm.x * (1.0f / 256.0f);
                    float rstd = rsqrtf(sm.y * (1.0f / 256.0f) - mu * mu + LN_EPS);
                    float4 gg = ((const float4*)lng)[kn / 4 + lc4];
                    float4 bb = ((const float4*)lnb)[kn / 4 + lc4];
                    v.x = (v.x - mu) * rstd * gg.x + bb.x;
                    v.y = (v.y - mu) * rstd * gg.y + bb.y;
                    v.z = (v.z - mu) * rstd * gg.z + bb.z;
                    v.w = (v.w - mu) * rstd * gg.w + bb.w;
                }
                ar[i] = v;
                br[i] = *(const float4*)(W + (size_t)(bn0 + row) * K + kn + lc4 * 4);
            }
        }

        #pragma unroll
        for (int ks = 0; ks < 2; ks++) {
            unsigned af[2][4], bfv[8][2];
            #pragma unroll
            for (int mt = 0; mt < 2; mt++)
                ldsm4(af[mt][0], af[mt][1], af[mt][2], af[mt][3], aAddr[mt] + ks * 32);
            #pragma unroll
            for (int nt2 = 0; nt2 < 4; nt2++) {
                unsigned r0, r1, r2, r3;
                ldsm4(r0, r1, r2, r3, bAddr[nt2] + ks * 32);
                bfv[nt2 * 2][0] = r0; bfv[nt2 * 2][1] = r1;
                bfv[nt2 * 2 + 1][0] = r2; bfv[nt2 * 2 + 1][1] = r3;
            }
            #pragma unroll
            for (int mt = 0; mt < 2; mt++)
                #pragma unroll
                for (int nt = 0; nt < 8; nt++)
                    mma_bf16(acc[mt][nt], af[mt], bfv[nt]);
        }
        __syncthreads();
    }

    #pragma unroll
    for (int mt = 0; mt < 2; mt++) {
        int r0 = bm0 + wm * 32 + mt * 16 + g;
        #pragma unroll
        for (int nt = 0; nt < 8; nt++) {
            int c0 = bn0 + wn * 64 + nt * 8 + 2 * tq;
            if (r0 < M)
                *(unsigned*)(C + (size_t)r0 * FFN + c0) = pack_bf16(acc[mt][nt][0], acc[mt][nt][1]);
            if (r0 + 8 < M)
                *(unsigned*)(C + (size_t)(r0 + 8) * FFN + c0) = pack_bf16(acc[mt][nt][2], acc[mt][nt][3]);
        }
    }
}

// ============================================================================
// GEMM3+gather fused (tf32): out[M,128] = (tanh(gcn(xw)) * h)[M,256] @ w_out^T + b_out
// BM=64, BN=128. K processed in 4 quarters of 64 cols:
//   gather phase: warp owns 8 rows; per row computes the GCN aggregation +
//   tanh gate for its 64-col slice and stores tf32 directly into As.
//   mma phase: standard B-tile + ldmatrix + mma consuming As.
// As pitch 68 (68 mod 32 = 4 -> conflict-free ldmatrix; 272B rows 16B-aligned).
// ============================================================================
__global__ __launch_bounds__(256) void k_gemm3g(
    const float* __restrict__ W, const float* __restrict__ bias,
    const float* __restrict__ bg, float* __restrict__ C, int M) {
    const int K = 256, N = 128, PA = 68, PB = 36;
    __shared__ float As[64 * PA];
    __shared__ float Bs[128 * PB];
    int tid = threadIdx.x;
    int wid = tid >> 5, lane = tid & 31;
    int wm = wid >> 1, wn = wid & 1;
    int g = lane >> 2, tq = lane & 3;
    int lrow8 = lane & 7, grp = lane >> 3;
    int bm0 = blockIdx.x * 64;

    float acc[8][4];
    #pragma unroll
    for (int nt = 0; nt < 8; nt++)
        #pragma unroll
        for (int i = 0; i < 4; i++) acc[nt][i] = 0.0f;

    unsigned aAddr, bAddr[4];
    {
        unsigned ab = (unsigned)__cvta_generic_to_shared(As);
        unsigned bb = (unsigned)__cvta_generic_to_shared(Bs);
        int rowA = wm * 16 + lrow8 + ((grp & 1) << 3);
        aAddr = ab + (rowA * PA + ((grp >> 1) << 2)) * 4;
        #pragma unroll
        for (int nt2 = 0; nt2 < 4; nt2++) {
            int rowB = wn * 64 + nt2 * 16 + lrow8 + ((grp >> 1) << 3);
            bAddr[nt2] = bb + (rowB * PB + ((grp & 1) << 2)) * 4;
        }
    }

    int lrow = tid >> 3, lc4 = tid & 7;
    const unsigned* xww = (const unsigned*)g_xw;   // bf16x2 word view (128/row)

    #pragma unroll 1
    for (int kq = 0; kq < 4; kq++) {
        int cbase = kq * 64;

        // ---- gather phase: warp wid handles rows wid*8 .. wid*8+7 ----
        #pragma unroll 1
        for (int i = 0; i < 8; i++) {
            int r = wid * 8 + i;
            int dst = bm0 + r;
            float a0 = 0.f, a1 = 0.f;
            if (dst < M) {
                float dvd = g_dinv[dst];
                float selfc = 2.0f * dvd * dvd;
                unsigned ws = xww[(size_t)dst * 128 + kq * 32 + lane];
                float2 vs = __bfloat1622float2(*(const __nv_bfloat162*)&ws);
                float2 bgv = *(const float2*)(bg + cbase + 2 * lane);
                a0 = bgv.x + selfc * vs.x;
                a1 = bgv.y + selfc * vs.y;

                int e = g_rowptr[dst], end = g_rowptr[dst + 1];
                for (; e + 8 <= end; e += 8) {
                    int   s[8]; float c[8]; unsigned q[8];
                    #pragma unroll
                    for (int j = 0; j < 8; j++) s[j] = g_csr[e + j];
                    #pragma unroll
                    for (int j = 0; j < 8; j++) c[j] = g_dinv[s[j]] * dvd;
                    #pragma unroll
                    for (int j = 0; j < 8; j++)
                        q[j] = xww[(size_t)s[j] * 128 + kq * 32 + lane];
                    #pragma unroll
                    for (int j = 0; j < 8; j++) {
                        float2 w2 = __bfloat1622float2(*(const __nv_bfloat162*)&q[j]);
                        a0 += c[j] * w2.x;
                        a1 += c[j] * w2.y;
                    }
                }
                for (; e < end; e++) {
                    int sgl = g_csr[e];
                    float c = g_dinv[sgl] * dvd;
                    unsigned q = xww[(size_t)sgl * 128 + kq * 32 + lane];
                    float2 w2 = __bfloat1622float2(*(const __nv_bfloat162*)&q);
                    a0 += c * w2.x;
                    a1 += c * w2.y;
                }
                float2 hv = *(const float2*)(g_h + (size_t)dst * 256 + cbase + 2 * lane);
                a0 = tanhf(a0) * hv.x;
                a1 = tanhf(a1) * hv.y;
            }
            As[r * PA + 2 * lane]     = f2tf32(a0);
            As[r * PA + 2 * lane + 1] = f2tf32(a1);
        }
        __syncthreads();

        // ---- mma phase: two 32-col B tiles per quarter ----
        #pragma unroll 1
        for (int kt = 0; kt < 2; kt++) {
            int k0 = cbase + kt * 32;
            #pragma unroll
            for (int i = 0; i < 4; i++) {
                float4 v = *(const float4*)(W + (size_t)(lrow + i * 32) * K + k0 + lc4 * 4);
                float* db = &Bs[(lrow + i * 32) * PB + lc4 * 4];
                db[0] = f2tf32(v.x); db[1] = f2tf32(v.y);
                db[2] = f2tf32(v.z); db[3] = f2tf32(v.w);
            }
            __syncthreads();

            #pragma unroll
            for (int ks = 0; ks < 4; ks++) {
                unsigned af[4], bfv[8][2];
                ldsm4(af[0], af[1], af[2], af[3], aAddr + kt * 128 + ks * 32);
                #pragma unroll
                for (int nt2 = 0; nt2 < 4; nt2++) {
                    unsigned r0, r1, r2, r3;
                    ldsm4(r0, r1, r2, r3, bAddr[nt2] + ks * 32);
                    bfv[nt2 * 2][0] = r0; bfv[nt2 * 2][1] = r1;
                    bfv[nt2 * 2 + 1][0] = r2; bfv[nt2 * 2 + 1][1] = r3;
                }
                #pragma unroll
                for (int nt = 0; nt < 8; nt++)
                    mma_tf32(acc[nt], af, bfv[nt]);
            }
            __syncthreads();   // before Bs (and, on kt==1, As) overwrite
        }
    }

    int r0 = bm0 + wm * 16 + g;
    #pragma unroll
    for (int nt = 0; nt < 8; nt++) {
        int c0 = wn * 64 + nt * 8 + 2 * tq;
        float bv0 = bias[c0], bv1 = bias[c0 + 1];
        if (r0 < M) {
            C[(size_t)r0 * N + c0]     = acc[nt][0] + bv0;
            C[(size_t)r0 * N + c0 + 1] = acc[nt][1] + bv1;
        }
        if (r0 + 8 < M) {
            C[(size_t)(r0 + 8) * N + c0]     = acc[nt][2] + bv0;
            C[(size_t)(r0 + 8) * N + c0 + 1] = acc[nt][3] + bv1;
        }
    }
}

// ---------------- host ------------------------------------------------------
extern "C" void kernel_launch(void* const* d_in, const int* in_sizes, int n_in,
                              void* d_out, int out_size) {
    const float* x     = (const float*)d_in[0];
    const void*  eidx  = d_in[1];
    const float* ln1_g = (const float*)d_in[2];
    const float* ln1_b = (const float*)d_in[3];
    const float* w_in  = (const float*)d_in[4];
    const float* b_in  = (const float*)d_in[5];
    const float* ln2_g = (const float*)d_in[6];
    const float* ln2_b = (const float*)d_in[7];
    const float* w_gcn = (const float*)d_in[8];
    const float* b_gcn = (const float*)d_in[9];
    const float* w_out = (const float*)d_in[10];
    const float* b_out = (const float*)d_in[11];
    float* out = (float*)d_out;

    int E = in_sizes[1] / 2;

    void *p_h, *p_xw, *p_st1, *p_st2;
    cudaGetSymbolAddress(&p_h,   g_h);
    cudaGetSymbolAddress(&p_xw,  g_xw);
    cudaGetSymbolAddress(&p_st1, g_st1);
    cudaGetSymbolAddress(&p_st2, g_st2);

    const int TB = 256;
    int eblk = (E + TB - 1) / TB;
    int wblk = (N_NODES * 32 + TB - 1) / TB;

    // 1. init: LN1 stats + zero hist/sums + dtype detect
    k_init<<<wblk, TB>>>(x, (const unsigned int*)eidx, 1024);

    // 2. GEMM1 (+ piggybacked edge histogram): x -> h (fp32), LN2 sums
    {
        dim3 grid((N_NODES + 127) / 128, FFN / 128 + 1);
        k_gemm1<<<grid, 256>>>(x, w_in, b_in, (float*)p_h, N_NODES,
                               (const float2*)p_st1, ln1_g, ln1_b, eidx, E);
    }

    // 3. GEMM2 (+ piggybacked scan1): h -> xw (bf16)
    {
        dim3 grid((N_NODES + 127) / 128, FFN / 128 + 1);
        k_gemm2<<<grid, 256>>>((const float*)p_h, w_gcn,
                               (__nv_bfloat16*)p_xw, N_NODES,
                               (const float2*)p_st2, ln2_g, ln2_b);
    }

    // 4. CSR tail: scan3 (rowptr offsets + dinv + cursors), fill
    k_scan3<<<NB_SCAN, 256>>>(E);
    k_fill <<<eblk, TB>>>(eidx, E);

    // 5. fused gather + gate + GEMM3: -> out
    {
        dim3 grid((N_NODES + 63) / 64, 1);
        k_gemm3g<<<grid, 256>>>(w_out, b_out, b_gcn, out, N_NODES);
    }
}

// round 17
// speedup vs baseline: 1.3774x; 1.3774x over previous
#include <cuda_runtime.h>
#include <cuda_bf16.h>
#include <math.h>
#include <stdint.h>

#define N_NODES 50000
#define HIDDEN  128
#define FFN     256
#define LN_EPS  1e-5f
#define MAX_E   524288
#define NB_SCAN 196   // ceil(50000/256)

// ---------------- scratch (static device globals; no allocation) ----------
__device__ __align__(16) float g_h [(size_t)N_NODES * FFN];          // gelu out (fp32)
__device__ __align__(16) __nv_bfloat16 g_xw[(size_t)N_NODES * FFN];  // gating gemm out
__device__ __align__(16) float g_hg[(size_t)N_NODES * FFN];          // tanh(agg)*h (tf32-rounded)
__device__ float  g_dinv[N_NODES];
__device__ int    g_cnt [N_NODES];
__device__ int    g_cur [N_NODES];
__device__ int    g_rowptr[N_NODES + 1];
__device__ int    g_bsum[256];
__device__ int    g_csr [MAX_E];
__device__ float2 g_st1[N_NODES];   // LN1 (mu, rstd) of x rows
__device__ float2 g_st2[N_NODES];   // (sum, sumsq) of h rows, filled by GEMM1
__device__ int    g_is64;

// ---------------- init: LN1 stats + zero hist/sums + dtype detect -----------
__global__ void k_init(const float* __restrict__ x, const unsigned int* __restrict__ w,
                       int nslots) {
    int gtid = blockIdx.x * blockDim.x + threadIdx.x;
    int warp = gtid >> 5;
    int lane = threadIdx.x & 31;

    if (gtid < N_NODES) {
        g_cnt[gtid] = 0;
        g_st2[gtid] = make_float2(0.f, 0.f);
    }
    if (warp < N_NODES) {
        float4 v = ((const float4*)(x + (size_t)warp * HIDDEN))[lane];
        float s  = v.x + v.y + v.z + v.w;
        float sq = v.x * v.x + v.y * v.y + v.z * v.z + v.w * v.w;
        #pragma unroll
        for (int o = 16; o; o >>= 1) {
            s  += __shfl_xor_sync(0xffffffffu, s,  o);
            sq += __shfl_xor_sync(0xffffffffu, sq, o);
        }
        if (lane == 0) {
            float mu  = s * (1.0f / HIDDEN);
            float var = sq * (1.0f / HIDDEN) - mu * mu;
            g_st1[warp] = make_float2(mu, rsqrtf(var + LN_EPS));
        }
    }
    if (blockIdx.x == 0) {
        __shared__ unsigned int red[256];
        unsigned int acc = 0;
        for (int j = threadIdx.x; j < nslots; j += blockDim.x) acc |= w[2 * j + 1];
        red[threadIdx.x] = acc;
        __syncthreads();
        for (int s = 128; s > 0; s >>= 1) {
            if (threadIdx.x < s) red[threadIdx.x] |= red[threadIdx.x + s];
            __syncthreads();
        }
        if (threadIdx.x == 0) g_is64 = (red[0] == 0u) ? 1 : 0;
    }
}

// ---------------- serial CSR tail -------------------------------------------
__global__ void k_scan3(int E) {
    __shared__ int sh[256];
    int t = threadIdx.x;
    int v = (t < NB_SCAN) ? g_bsum[t] : 0;
    sh[t] = v;
    __syncthreads();
    #pragma unroll
    for (int off = 1; off < 256; off <<= 1) {
        int addend = (t >= off) ? sh[t - off] : 0;
        __syncthreads();
        sh[t] += addend;
        __syncthreads();
    }
    int boff = (blockIdx.x > 0) ? sh[blockIdx.x - 1] : 0;
    int i = blockIdx.x * 256 + t;
    if (i < N_NODES) {
        g_rowptr[i] += boff;
        g_dinv[i] = rsqrtf((float)g_cnt[i] + 2.0f);
        g_cur[i] = 0;
    }
    if (i == 0) g_rowptr[N_NODES] = E;
}
__global__ void k_fill(const void* __restrict__ eidx, int E) {
    int e = blockIdx.x * blockDim.x + threadIdx.x;
    if (e >= E) return;
    int s, d;
    if (g_is64) {
        const long long* p = (const long long*)eidx;
        s = (int)p[e]; d = (int)p[E + e];
    } else {
        const int* p = (const int*)eidx;
        s = p[e]; d = p[E + e];
    }
    int pos = g_rowptr[d] + atomicAdd(&g_cur[d], 1);
    g_csr[pos] = s;
}

// ---------------- mma / ldmatrix helpers ------------------------------------
__device__ __forceinline__ float f2tf32(float x) {
    unsigned r;
    asm("cvt.rna.tf32.f32 %0, %1;" : "=r"(r) : "f"(x));
    return __uint_as_float(r);
}
__device__ __forceinline__ void mma_tf32(float* c, const unsigned* a, const unsigned* b) {
    asm volatile(
        "mma.sync.aligned.m16n8k8.row.col.f32.tf32.tf32.f32 "
        "{%0,%1,%2,%3}, {%4,%5,%6,%7}, {%8,%9}, {%0,%1,%2,%3};"
        : "+f"(c[0]), "+f"(c[1]), "+f"(c[2]), "+f"(c[3])
        : "r"(a[0]), "r"(a[1]), "r"(a[2]), "r"(a[3]), "r"(b[0]), "r"(b[1]));
}
__device__ __forceinline__ void mma_bf16(float* c, const unsigned* a, const unsigned* b) {
    asm volatile(
        "mma.sync.aligned.m16n8k16.row.col.f32.bf16.bf16.f32 "
        "{%0,%1,%2,%3}, {%4,%5,%6,%7}, {%8,%9}, {%0,%1,%2,%3};"
        : "+f"(c[0]), "+f"(c[1]), "+f"(c[2]), "+f"(c[3])
        : "r"(a[0]), "r"(a[1]), "r"(a[2]), "r"(a[3]), "r"(b[0]), "r"(b[1]));
}
__device__ __forceinline__ unsigned pack_bf16(float a, float b) {
    unsigned r;
    asm("cvt.rn.bf16x2.f32 %0, %1, %2;" : "=r"(r) : "f"(b), "f"(a));
    return r;
}
__device__ __forceinline__ void ldsm4(unsigned& r0, unsigned& r1, unsigned& r2,
                                      unsigned& r3, unsigned addr) {
    asm volatile("ldmatrix.sync.aligned.m8n8.x4.shared.b16 {%0,%1,%2,%3}, [%4];"
                 : "=r"(r0), "=r"(r1), "=r"(r2), "=r"(r3) : "r"(addr));
}
__device__ __forceinline__ float gelu_f(float v) {
    return 0.5f * v * (1.0f + erff(v * 0.70710678118654752f));
}

// ============================================================================
// GEMM1 (tf32): h_f32[M,256] = gelu(LN1(x)[M,128] @ w_in^T + b_in)
// Accumulates per-row (sum, sumsq) of gelu output into g_st2 (LN2 stats).
// Grid (391, 3): y in {0,1} = GEMM tiles; y == 2 = edge-histogram blocks.
// ============================================================================
__global__ __launch_bounds__(256) void k_gemm1(
    const float* __restrict__ A, const float* __restrict__ W,
    const float* __restrict__ bias, float* __restrict__ C, int M,
    const float2* __restrict__ stats, const float* __restrict__ lng,
    const float* __restrict__ lnb, const void* __restrict__ eidx, int E) {
    const int K = 128, BK = 32, PITCH = 36;
    __shared__ float As[128 * PITCH];
    __shared__ float Bs[128 * PITCH];

    // ---- piggyback: histogram of destination nodes ----
    if (blockIdx.y == 2) {
        int stride = gridDim.x * blockDim.x;
        if (g_is64) {
            const long long* p = (const long long*)eidx;
            for (int e = blockIdx.x * blockDim.x + threadIdx.x; e < E; e += stride)
                atomicAdd(&g_cnt[(int)p[E + e]], 1);
        } else {
            const int* p = (const int*)eidx;
            for (int e = blockIdx.x * blockDim.x + threadIdx.x; e < E; e += stride)
                atomicAdd(&g_cnt[p[E + e]], 1);
        }
        return;
    }

    int tid = threadIdx.x;
    int wid = tid >> 5, lane = tid & 31;
    int wm = wid >> 1, wn = wid & 1;
    int g = lane >> 2, tq = lane & 3;
    int lrow8 = lane & 7, grp = lane >> 3;
    int bm0 = blockIdx.x * 128, bn0 = blockIdx.y * 128;

    float acc[2][8][4];
    #pragma unroll
    for (int mt = 0; mt < 2; mt++)
        #pragma unroll
        for (int nt = 0; nt < 8; nt++)
            #pragma unroll
            for (int i = 0; i < 4; i++) acc[mt][nt][i] = 0.0f;

    unsigned aAddr[2], bAddr[4];
    {
        unsigned ab = (unsigned)__cvta_generic_to_shared(As);
        unsigned bb = (unsigned)__cvta_generic_to_shared(Bs);
        #pragma unroll
        for (int mt = 0; mt < 2; mt++) {
            int rowA = wm * 32 + mt * 16 + lrow8 + ((grp & 1) << 3);
            aAddr[mt] = ab + (rowA * PITCH + ((grp >> 1) << 2)) * 4;
        }
        #pragma unroll
        for (int nt2 = 0; nt2 < 4; nt2++) {
            int rowB = wn * 64 + nt2 * 16 + lrow8 + ((grp >> 1) << 3);
            bAddr[nt2] = bb + (rowB * PITCH + ((grp & 1) << 2)) * 4;
        }
    }

    int lrow = tid >> 3, lc4 = tid & 7;
    float4 ar[4], br[4];

    #pragma unroll
    for (int i = 0; i < 4; i++) {
        int row = lrow + i * 32;
        int gr = bm0 + row;
        float4 v = make_float4(0.f, 0.f, 0.f, 0.f);
        if (gr < M) {
            v = *(const float4*)(A + (size_t)gr * K + lc4 * 4);
            float2 st = stats[gr];
            float4 gg = ((const float4*)lng)[lc4];
            float4 bb = ((const float4*)lnb)[lc4];
            v.x = (v.x - st.x) * st.y * gg.x + bb.x;
            v.y = (v.y - st.x) * st.y * gg.y + bb.y;
            v.z = (v.z - st.x) * st.y * gg.z + bb.z;
            v.w = (v.w - st.x) * st.y * gg.w + bb.w;
        }
        ar[i] = v;
        br[i] = *(const float4*)(W + (size_t)(bn0 + row) * K + lc4 * 4);
    }

    #pragma unroll 1
    for (int k0 = 0; k0 < K; k0 += BK) {
        #pragma unroll
        for (int i = 0; i < 4; i++) {
            int row = lrow + i * 32;
            float* da = &As[row * PITCH + lc4 * 4];
            da[0] = f2tf32(ar[i].x); da[1] = f2tf32(ar[i].y);
            da[2] = f2tf32(ar[i].z); da[3] = f2tf32(ar[i].w);
            float* db = &Bs[row * PITCH + lc4 * 4];
            db[0] = f2tf32(br[i].x); db[1] = f2tf32(br[i].y);
            db[2] = f2tf32(br[i].z); db[3] = f2tf32(br[i].w);
        }
        __syncthreads();

        if (k0 + BK < K) {
            int kn = k0 + BK;
            #pragma unroll
            for (int i = 0; i < 4; i++) {
                int row = lrow + i * 32;
                int gr = bm0 + row;
                float4 v = make_float4(0.f, 0.f, 0.f, 0.f);
                if (gr < M) {
                    v = *(const float4*)(A + (size_t)gr * K + kn + lc4 * 4);
                    float2 st = stats[gr];
                    float4 gg = ((const float4*)lng)[kn / 4 + lc4];
                    float4 bb = ((const float4*)lnb)[kn / 4 + lc4];
                    v.x = (v.x - st.x) * st.y * gg.x + bb.x;
                    v.y = (v.y - st.x) * st.y * gg.y + bb.y;
                    v.z = (v.z - st.x) * st.y * gg.z + bb.z;
                    v.w = (v.w - st.x) * st.y * gg.w + bb.w;
                }
                ar[i] = v;
                br[i] = *(const float4*)(W + (size_t)(bn0 + row) * K + kn + lc4 * 4);
            }
        }

        #pragma unroll
        for (int ks = 0; ks < 4; ks++) {
            unsigned af[2][4], bfv[8][2];
            #pragma unroll
            for (int mt = 0; mt < 2; mt++)
                ldsm4(af[mt][0], af[mt][1], af[mt][2], af[mt][3], aAddr[mt] + ks * 32);
            #pragma unroll
            for (int nt2 = 0; nt2 < 4; nt2++) {
                unsigned r0, r1, r2, r3;
                ldsm4(r0, r1, r2, r3, bAddr[nt2] + ks * 32);
                bfv[nt2 * 2][0] = r0; bfv[nt2 * 2][1] = r1;
                bfv[nt2 * 2 + 1][0] = r2; bfv[nt2 * 2 + 1][1] = r3;
            }
            #pragma unroll
            for (int mt = 0; mt < 2; mt++)
                #pragma unroll
                for (int nt = 0; nt < 8; nt++)
                    mma_tf32(acc[mt][nt], af[mt], bfv[nt]);
        }
        __syncthreads();
    }

    // epilogue: gelu -> fp32 store + per-row (sum, sumsq) accumulation
    #pragma unroll
    for (int mt = 0; mt < 2; mt++) {
        #pragma unroll
        for (int half = 0; half < 2; half++) {
            int r = bm0 + wm * 32 + mt * 16 + half * 8 + g;
            float s = 0.f, sq = 0.f;
            float v0s[8], v1s[8];
            #pragma unroll
            for (int nt = 0; nt < 8; nt++) {
                int c0 = bn0 + wn * 64 + nt * 8 + 2 * tq;
                float v0 = gelu_f(acc[mt][nt][half * 2 + 0] + bias[c0]);
                float v1 = gelu_f(acc[mt][nt][half * 2 + 1] + bias[c0 + 1]);
                v0s[nt] = v0; v1s[nt] = v1;
                s += v0 + v1;
                sq += v0 * v0 + v1 * v1;
            }
            if (r < M) {
                #pragma unroll
                for (int nt = 0; nt < 8; nt++) {
                    int c0 = bn0 + wn * 64 + nt * 8 + 2 * tq;
                    C[(size_t)r * FFN + c0]     = v0s[nt];
                    C[(size_t)r * FFN + c0 + 1] = v1s[nt];
                }
            }
            s  += __shfl_xor_sync(0xffffffffu, s, 1);
            s  += __shfl_xor_sync(0xffffffffu, s, 2);
            sq += __shfl_xor_sync(0xffffffffu, sq, 1);
            sq += __shfl_xor_sync(0xffffffffu, sq, 2);
            if (tq == 0 && r < M) {
                atomicAdd(&g_st2[r].x, s);
                atomicAdd(&g_st2[r].y, sq);
            }
        }
    }
}

// ============================================================================
// GEMM2 (bf16 mma): xw_bf16[M,256] = LN2(h)[M,256] @ w_gcn^T
// Grid (391, 3): y in {0,1} = GEMM tiles; y == 2, x < 196 = scan1 blocks.
// ============================================================================
__global__ __launch_bounds__(256) void k_gemm2(
    const float* __restrict__ A, const float* __restrict__ W,
    __nv_bfloat16* __restrict__ C, int M,
    const float2* __restrict__ sums, const float* __restrict__ lng,
    const float* __restrict__ lnb) {
    const int K = 256, BK = 32, PW = 20;
    __shared__ unsigned As[128 * PW];
    __shared__ unsigned Bs[128 * PW];

    // ---- piggyback: scan1 (hist complete at previous kernel boundary) ----
    if (blockIdx.y == 2) {
        if (blockIdx.x >= NB_SCAN) return;
        int* sh = (int*)As;
        int t = threadIdx.x;
        int i = blockIdx.x * 256 + t;
        int v = (i < N_NODES) ? g_cnt[i] : 0;
        sh[t] = v;
        __syncthreads();
        #pragma unroll
        for (int off = 1; off < 256; off <<= 1) {
            int addend = (t >= off) ? sh[t - off] : 0;
            __syncthreads();
            sh[t] += addend;
            __syncthreads();
        }
        if (i < N_NODES) g_rowptr[i] = sh[t] - v;
        if (t == 255) g_bsum[blockIdx.x] = sh[255];
        return;
    }

    int tid = threadIdx.x;
    int wid = tid >> 5, lane = tid & 31;
    int wm = wid >> 1, wn = wid & 1;
    int g = lane >> 2, tq = lane & 3;
    int lrow8 = lane & 7, grp = lane >> 3;
    int bm0 = blockIdx.x * 128, bn0 = blockIdx.y * 128;

    float acc[2][8][4];
    #pragma unroll
    for (int mt = 0; mt < 2; mt++)
        #pragma unroll
        for (int nt = 0; nt < 8; nt++)
            #pragma unroll
            for (int i = 0; i < 4; i++) acc[mt][nt][i] = 0.0f;

    unsigned aAddr[2], bAddr[4];
    {
        unsigned ab = (unsigned)__cvta_generic_to_shared(As);
        unsigned bb = (unsigned)__cvta_generic_to_shared(Bs);
        #pragma unroll
        for (int mt = 0; mt < 2; mt++) {
            int rowA = wm * 32 + mt * 16 + lrow8 + ((grp & 1) << 3);
            aAddr[mt] = ab + rowA * (PW * 4) + ((grp >> 1) << 4);
        }
        #pragma unroll
        for (int nt2 = 0; nt2 < 4; nt2++) {
            int rowB = wn * 64 + nt2 * 16 + lrow8 + ((grp >> 1) << 3);
            bAddr[nt2] = bb + rowB * (PW * 4) + ((grp & 1) << 4);
        }
    }

    int lrow = tid >> 3, lc4 = tid & 7;
    float4 ar[4], br[4];

    #pragma unroll
    for (int i = 0; i < 4; i++) {
        int row = lrow + i * 32;
        int gr = bm0 + row;
        float4 v = make_float4(0.f, 0.f, 0.f, 0.f);
        if (gr < M) {
            v = *(const float4*)(A + (size_t)gr * K + lc4 * 4);
            float2 sm = sums[gr];
            float mu = sm.x * (1.0f / 256.0f);
            float rstd = rsqrtf(sm.y * (1.0f / 256.0f) - mu * mu + LN_EPS);
            float4 gg = ((const float4*)lng)[lc4];
            float4 bb = ((const float4*)lnb)[lc4];
            v.x = (v.x - mu) * rstd * gg.x + bb.x;
            v.y = (v.y - mu) * rstd * gg.y + bb.y;
            v.z = (v.z - mu) * rstd * gg.z + bb.z;
            v.w = (v.w - mu) * rstd * gg.w + bb.w;
        }
        ar[i] = v;
        br[i] = *(const float4*)(W + (size_t)(bn0 + row) * K + lc4 * 4);
    }

    #pragma unroll 1
    for (int k0 = 0; k0 < K; k0 += BK) {
        #pragma unroll
        for (int i = 0; i < 4; i++) {
            int row = lrow + i * 32;
            As[row * PW + lc4 * 2]     = pack_bf16(ar[i].x, ar[i].y);
            As[row * PW + lc4 * 2 + 1] = pack_bf16(ar[i].z, ar[i].w);
            Bs[row * PW + lc4 * 2]     = pack_bf16(br[i].x, br[i].y);
            Bs[row * PW + lc4 * 2 + 1] = pack_bf16(br[i].z, br[i].w);
        }
        __syncthreads();

        if (k0 + BK < K) {
            int kn = k0 + BK;
            #pragma unroll
            for (int i = 0; i < 4; i++) {
                int row = lrow + i * 32;
                int gr = bm0 + row;
                float4 v = make_float4(0.f, 0.f, 0.f, 0.f);
                if (gr < M) {
                    v = *(const float4*)(A + (size_t)gr * K + kn + lc4 * 4);
                    float2 sm = sums[gr];
                    float mu = sm.x * (1.0f / 256.0f);
                    float rstd = rsqrtf(sm.y * (1.0f / 256.0f) - mu * mu + LN_EPS);
                    float4 gg = ((const float4*)lng)[kn / 4 + lc4];
                    float4 bb = ((const float4*)lnb)[kn / 4 + lc4];
                    v.x = (v.x - mu) * rstd * gg.x + bb.x;
                    v.y = (v.y - mu) * rstd * gg.y + bb.y;
                    v.z = (v.z - mu) * rstd * gg.z + bb.z;
                    v.w = (v.w - mu) * rstd * gg.w + bb.w;
                }
                ar[i] = v;
                br[i] = *(const float4*)(W + (size_t)(bn0 + row) * K + kn + lc4 * 4);
            }
        }

        #pragma unroll
        for (int ks = 0; ks < 2; ks++) {
            unsigned af[2][4], bfv[8][2];
            #pragma unroll
            for (int mt = 0; mt < 2; mt++)
                ldsm4(af[mt][0], af[mt][1], af[mt][2], af[mt][3], aAddr[mt] + ks * 32);
            #pragma unroll
            for (int nt2 = 0; nt2 < 4; nt2++) {
                unsigned r0, r1, r2, r3;
                ldsm4(r0, r1, r2, r3, bAddr[nt2] + ks * 32);
                bfv[nt2 * 2][0] = r0; bfv[nt2 * 2][1] = r1;
                bfv[nt2 * 2 + 1][0] = r2; bfv[nt2 * 2 + 1][1] = r3;
            }
            #pragma unroll
            for (int mt = 0; mt < 2; mt++)
                #pragma unroll
                for (int nt = 0; nt < 8; nt++)
                    mma_bf16(acc[mt][nt], af[mt], bfv[nt]);
        }
        __syncthreads();
    }

    #pragma unroll
    for (int mt = 0; mt < 2; mt++) {
        int r0 = bm0 + wm * 32 + mt * 16 + g;
        #pragma unroll
        for (int nt = 0; nt < 8; nt++) {
            int c0 = bn0 + wn * 64 + nt * 8 + 2 * tq;
            if (r0 < M)
                *(unsigned*)(C + (size_t)r0 * FFN + c0) = pack_bf16(acc[mt][nt][0], acc[mt][nt][1]);
            if (r0 + 8 < M)
                *(unsigned*)(C + (size_t)(r0 + 8) * FFN + c0) = pack_bf16(acc[mt][nt][2], acc[mt][nt][3]);
        }
    }
}

// ============================================================================
// GEMM3 (tf32): out[M,128] = hg[M,256] @ w_out^T + b_out
// hg is already tf32-rounded by k_gather -> A loader skips cvt.
// BM=64, BN=128, BK=32, 256 threads, warp grid 4x2, warp tile 16x64.
// ============================================================================
__global__ __launch_bounds__(256) void k_gemm3(
    const float* __restrict__ A, const float* __restrict__ W,
    const float* __restrict__ bias, float* __restrict__ C, int M) {
    const int K = 256, N = 128, BK = 32, PITCH = 36, BM = 64;
    __shared__ float As[BM * PITCH];
    __shared__ float Bs[128 * PITCH];
    int tid = threadIdx.x;
    int wid = tid >> 5, lane = tid & 31;
    int wm = wid >> 1, wn = wid & 1;
    int g = lane >> 2, tq = lane & 3;
    int lrow8 = lane & 7, grp = lane >> 3;
    int bm0 = blockIdx.x * BM, bn0 = 0;

    float acc[8][4];
    #pragma unroll
    for (int nt = 0; nt < 8; nt++)
        #pragma unroll
        for (int i = 0; i < 4; i++) acc[nt][i] = 0.0f;

    unsigned aAddr, bAddr[4];
    {
        unsigned ab = (unsigned)__cvta_generic_to_shared(As);
        unsigned bb = (unsigned)__cvta_generic_to_shared(Bs);
        int rowA = wm * 16 + lrow8 + ((grp & 1) << 3);
        aAddr = ab + (rowA * PITCH + ((grp >> 1) << 2)) * 4;
        #pragma unroll
        for (int nt2 = 0; nt2 < 4; nt2++) {
            int rowB = wn * 64 + nt2 * 16 + lrow8 + ((grp >> 1) << 3);
            bAddr[nt2] = bb + (rowB * PITCH + ((grp & 1) << 2)) * 4;
        }
    }

    int lrow = tid >> 3, lc4 = tid & 7;
    float4 ar[2], br[4];

    #pragma unroll
    for (int i = 0; i < 2; i++) {
        int gr = bm0 + lrow + i * 32;
        ar[i] = (gr < M) ? *(const float4*)(A + (size_t)gr * K + lc4 * 4)
                         : make_float4(0.f, 0.f, 0.f, 0.f);
    }
    #pragma unroll
    for (int i = 0; i < 4; i++)
        br[i] = *(const float4*)(W + (size_t)(bn0 + lrow + i * 32) * K + lc4 * 4);

    #pragma unroll 1
    for (int k0 = 0; k0 < K; k0 += BK) {
        #pragma unroll
        for (int i = 0; i < 2; i++) {
            // hg already tf32-rounded: plain store
            *(float4*)&As[(lrow + i * 32) * PITCH + lc4 * 4] = ar[i];
        }
        #pragma unroll
        for (int i = 0; i < 4; i++) {
            float* db = &Bs[(lrow + i * 32) * PITCH + lc4 * 4];
            db[0] = f2tf32(br[i].x); db[1] = f2tf32(br[i].y);
            db[2] = f2tf32(br[i].z); db[3] = f2tf32(br[i].w);
        }
        __syncthreads();

        if (k0 + BK < K) {
            int kn = k0 + BK;
            #pragma unroll
            for (int i = 0; i < 2; i++) {
                int gr = bm0 + lrow + i * 32;
                ar[i] = (gr < M) ? *(const float4*)(A + (size_t)gr * K + kn + lc4 * 4)
                                 : make_float4(0.f, 0.f, 0.f, 0.f);
            }
            #pragma unroll
            for (int i = 0; i < 4; i++)
                br[i] = *(const float4*)(W + (size_t)(bn0 + lrow + i * 32) * K + kn + lc4 * 4);
        }

        #pragma unroll
        for (int ks = 0; ks < 4; ks++) {
            unsigned af[4], bfv[8][2];
            ldsm4(af[0], af[1], af[2], af[3], aAddr + ks * 32);
            #pragma unroll
            for (int nt2 = 0; nt2 < 4; nt2++) {
                unsigned r0, r1, r2, r3;
                ldsm4(r0, r1, r2, r3, bAddr[nt2] + ks * 32);
                bfv[nt2 * 2][0] = r0; bfv[nt2 * 2][1] = r1;
                bfv[nt2 * 2 + 1][0] = r2; bfv[nt2 * 2 + 1][1] = r3;
            }
            #pragma unroll
            for (int nt = 0; nt < 8; nt++)
                mma_tf32(acc[nt], af, bfv[nt]);
        }
        __syncthreads();
    }

    int r0 = bm0 + wm * 16 + g;
    #pragma unroll
    for (int nt = 0; nt < 8; nt++) {
        int c0 = bn0 + wn * 64 + nt * 8 + 2 * tq;
        float bv0 = bias[c0], bv1 = bias[c0 + 1];
        if (r0 < M) {
            C[(size_t)r0 * N + c0]     = acc[nt][0] + bv0;
            C[(size_t)r0 * N + c0 + 1] = acc[nt][1] + bv1;
        }
        if (r0 + 8 < M) {
            C[(size_t)(r0 + 8) * N + c0]     = acc[nt][2] + bv0;
            C[(size_t)(r0 + 8) * N + c0 + 1] = acc[nt][3] + bv1;
        }
    }
}

// ---------------- fused GCN gather + gate (bf16 xw, fp32 h -> tf32 hg) ------
__global__ __launch_bounds__(256) void k_gather(const float* __restrict__ bg) {
    int warp = (blockIdx.x * blockDim.x + threadIdx.x) >> 5;
    if (warp >= N_NODES) return;
    int lane = threadIdx.x & 31;

    float dvd = g_dinv[warp];
    float selfc = 2.0f * dvd * dvd;

    float a[8];
    {
        float4 b0 = ((const float4*)bg)[2 * lane];
        float4 b1 = ((const float4*)bg)[2 * lane + 1];
        uint4 q = ((const uint4*)(g_xw + (size_t)warp * FFN))[lane];
        const __nv_bfloat162* p = (const __nv_bfloat162*)&q;
        float2 v0 = __bfloat1622float2(p[0]);
        float2 v1 = __bfloat1622float2(p[1]);
        float2 v2 = __bfloat1622float2(p[2]);
        float2 v3 = __bfloat1622float2(p[3]);
        a[0] = b0.x + selfc * v0.x; a[1] = b0.y + selfc * v0.y;
        a[2] = b0.z + selfc * v1.x; a[3] = b0.w + selfc * v1.y;
        a[4] = b1.x + selfc * v2.x; a[5] = b1.y + selfc * v2.y;
        a[6] = b1.z + selfc * v3.x; a[7] = b1.w + selfc * v3.y;
    }

    int e   = g_rowptr[warp];
    int end = g_rowptr[warp + 1];

    for (; e + 4 <= end; e += 4) {
        int s0 = g_csr[e], s1 = g_csr[e + 1], s2 = g_csr[e + 2], s3 = g_csr[e + 3];
        float c0 = g_dinv[s0] * dvd, c1 = g_dinv[s1] * dvd;
        float c2 = g_dinv[s2] * dvd, c3 = g_dinv[s3] * dvd;
        uint4 q0 = ((const uint4*)(g_xw + (size_t)s0 * FFN))[lane];
        uint4 q1 = ((const uint4*)(g_xw + (size_t)s1 * FFN))[lane];
        uint4 q2 = ((const uint4*)(g_xw + (size_t)s2 * FFN))[lane];
        uint4 q3 = ((const uint4*)(g_xw + (size_t)s3 * FFN))[lane];
        #pragma unroll
        for (int j = 0; j < 4; j++) {
            float2 w0 = __bfloat1622float2(((const __nv_bfloat162*)&q0)[j]);
            float2 w1 = __bfloat1622float2(((const __nv_bfloat162*)&q1)[j]);
            float2 w2 = __bfloat1622float2(((const __nv_bfloat162*)&q2)[j]);
            float2 w3 = __bfloat1622float2(((const __nv_bfloat162*)&q3)[j]);
            a[2*j]   += c0 * w0.x + c1 * w1.x + c2 * w2.x + c3 * w3.x;
            a[2*j+1] += c0 * w0.y + c1 * w1.y + c2 * w2.y + c3 * w3.y;
        }
    }
    for (; e < end; e++) {
        int s = g_csr[e];
        float c = g_dinv[s] * dvd;
        uint4 q = ((const uint4*)(g_xw + (size_t)s * FFN))[lane];
        #pragma unroll
        for (int j = 0; j < 4; j++) {
            float2 w = __bfloat1622float2(((const __nv_bfloat162*)&q)[j]);
            a[2*j]   += c * w.x;
            a[2*j+1] += c * w.y;
        }
    }

    // gate: hg = tf32(tanh(a) * h)  (pre-rounded for GEMM3's A path)
    const float4* hd = (const float4*)(g_h + (size_t)warp * FFN);
    float4* hgd = (float4*)(g_hg + (size_t)warp * FFN);
    #pragma unroll
    for (int j = 0; j < 2; j++) {
        float4 h = hd[2 * lane + j];
        float4 o;
        o.x = f2tf32(tanhf(a[4*j + 0]) * h.x);
        o.y = f2tf32(tanhf(a[4*j + 1]) * h.y);
        o.z = f2tf32(tanhf(a[4*j + 2]) * h.z);
        o.w = f2tf32(tanhf(a[4*j + 3]) * h.w);
        hgd[2 * lane + j] = o;
    }
}

// ---------------- host ------------------------------------------------------
extern "C" void kernel_launch(void* const* d_in, const int* in_sizes, int n_in,
                              void* d_out, int out_size) {
    const float* x     = (const float*)d_in[0];
    const void*  eidx  = d_in[1];
    const float* ln1_g = (const float*)d_in[2];
    const float* ln1_b = (const float*)d_in[3];
    const float* w_in  = (const float*)d_in[4];
    const float* b_in  = (const float*)d_in[5];
    const float* ln2_g = (const float*)d_in[6];
    const float* ln2_b = (const float*)d_in[7];
    const float* w_gcn = (const float*)d_in[8];
    const float* b_gcn = (const float*)d_in[9];
    const float* w_out = (const float*)d_in[10];
    const float* b_out = (const float*)d_in[11];
    float* out = (float*)d_out;

    int E = in_sizes[1] / 2;

    void *p_h, *p_xw, *p_hg, *p_st1, *p_st2;
    cudaGetSymbolAddress(&p_h,   g_h);
    cudaGetSymbolAddress(&p_xw,  g_xw);
    cudaGetSymbolAddress(&p_hg,  g_hg);
    cudaGetSymbolAddress(&p_st1, g_st1);
    cudaGetSymbolAddress(&p_st2, g_st2);

    const int TB = 256;
    int eblk = (E + TB - 1) / TB;
    int wblk = (N_NODES * 32 + TB - 1) / TB;

    // 1. init: LN1 stats + zero hist/sums + dtype detect
    k_init<<<wblk, TB>>>(x, (const unsigned int*)eidx, 1024);

    // 2. GEMM1 (+ piggybacked edge histogram): x -> h (fp32), LN2 sums
    {
        dim3 grid((N_NODES + 127) / 128, FFN / 128 + 1);
        k_gemm1<<<grid, 256>>>(x, w_in, b_in, (float*)p_h, N_NODES,
                               (const float2*)p_st1, ln1_g, ln1_b, eidx, E);
    }

    // 3. GEMM2 (+ piggybacked scan1): h -> xw (bf16)
    {
        dim3 grid((N_NODES + 127) / 128, FFN / 128 + 1);
        k_gemm2<<<grid, 256>>>((const float*)p_h, w_gcn,
                               (__nv_bfloat16*)p_xw, N_NODES,
                               (const float2*)p_st2, ln2_g, ln2_b);
    }

    // 4. CSR tail: scan3 (rowptr offsets + dinv + cursors), fill
    k_scan3<<<NB_SCAN, 256>>>(E);
    k_fill <<<eblk, TB>>>(eidx, E);

    // 5. fused gather + self-loop + bias + tanh-gate: -> hg (tf32-rounded)
    k_gather<<<wblk, TB>>>(b_gcn);

    // 6. GEMM3 (tf32, BM=64): hg -> out
    {
        dim3 grid((N_NODES + 63) / 64, 1);
        k_gemm3<<<grid, 256>>>((const float*)p_hg, w_out, b_out, out, N_NODES);
    }
}